// round 13
// baseline (speedup 1.0000x reference)
#include <cuda_runtime.h>

#define HH 512
#define WW 512
#define CC 64
#define RROWS 32

__device__ float g_scales[192];

__global__ void softplus_kernel(const float* __restrict__ D) {
    int i = threadIdx.x;
    if (i < 192) {
        float x = D[i];
        g_scales[i] = (x > 20.0f) ? x : log1pf(expf(x));
    }
}

__device__ __forceinline__ float4 ld4(const float* __restrict__ p) {
    return *reinterpret_cast<const float4*>(p);
}
__device__ __forceinline__ float4 f4all(float v) {
    return make_float4(v, v, v, v);
}

__global__ __launch_bounds__(128, 7) void lap_kernel(const float* __restrict__ u,
                                                     float* __restrict__ out) {
    const int lane = threadIdx.x;                 // 0..31
    const int span = threadIdx.y;                 // 0..3
    const int x0   = (span << 7) + (lane << 2);   // this thread's float4 x
    const int y0   = blockIdx.y * RROWS;
    const int img  = blockIdx.z;
    const int ch   = img & (CC - 1);

    const float* __restrict__ base = u + (size_t)img * (HH * WW);
    float* __restrict__ ob = out + (size_t)img * (HH * WW);

    const float s0 = g_scales[ch];
    const float s1 = g_scales[64 + ch];
    const float s2 = g_scales[128 + ch];
    const float sm4 = -4.0f * (s0 + s1 + s2);

    // branchless clamped x-offsets (uniform per thread, hoisted)
    const int  xl4   = max(x0 - 4, 0);
    const int  xr4   = min(x0 + 4, WW - 4);
    const int  xl16  = max(x0 - 16, 0);
    const int  xr16  = min(x0 + 16, WW - 4);
    const bool okl4  = (x0 >= 4);
    const bool okr4  = (x0 + 4 < WW);
    const bool okl16 = (x0 >= 16);
    const bool okr16 = (x0 + 16 < WW);

    // circular 9-row window: slot (t+i)%9 = row y0+t-4+i (clamped)
    float4 w[9];
#pragma unroll
    for (int i = 0; i < 9; i++) {
        int r = y0 + i - 4;
        r = min(max(r, 0), HH - 1);
        w[i] = ld4(base + r * WW + x0);
    }

#pragma unroll
    for (int t = 0; t < RROWS; t++) {
        const int y = y0 + t;
        const float* __restrict__ rowc = base + y * WW;

        // ---- all 6 independent loads issued upfront (MLP) ----
        const float4 u16  = ld4(base + max(y - 16, 0) * WW + x0);
        const float4 d16  = ld4(base + min(y + 16, HH - 1) * WW + x0);
        const float4 l16r = ld4(rowc + xl16);
        const float4 r16r = ld4(rowc + xr16);
        const float4 l4r  = ld4(rowc + xl4);
        const float4 r4r  = ld4(rowc + xr4);

        const float4 c = w[(t + 4) % 9];

        // ---- d=16 contribution ----
        float4 a;
        {
            const float4 l16 = okl16 ? l16r : f4all(l16r.x);
            const float4 r16 = okr16 ? r16r : f4all(r16r.w);
            a.x = fmaf(s2, (u16.x + d16.x) + (l16.x + r16.x), sm4 * c.x);
            a.y = fmaf(s2, (u16.y + d16.y) + (l16.y + r16.y), sm4 * c.y);
            a.z = fmaf(s2, (u16.z + d16.z) + (l16.z + r16.z), sm4 * c.z);
            a.w = fmaf(s2, (u16.w + d16.w) + (l16.w + r16.w), sm4 * c.w);
        }

        // ---- d=4 contribution (verticals from window) ----
        {
            const float4 u4v = w[t % 9];
            const float4 d4v = w[(t + 8) % 9];
            const float4 l4 = okl4 ? l4r : f4all(l4r.x);
            const float4 r4 = okr4 ? r4r : f4all(r4r.w);
            a.x = fmaf(s1, (u4v.x + d4v.x) + (l4.x + r4.x), a.x);
            a.y = fmaf(s1, (u4v.y + d4v.y) + (l4.y + r4.y), a.y);
            a.z = fmaf(s1, (u4v.z + d4v.z) + (l4.z + r4.z), a.z);
            a.w = fmaf(s1, (u4v.w + d4v.w) + (l4.w + r4.w), a.w);
        }

        // ---- d=1 contribution (verticals from window; horiz from l4r/r4r) ----
        {
            const float4 u1 = w[(t + 3) % 9];
            const float4 d1 = w[(t + 5) % 9];
            const float l1 = okl4 ? l4r.w : l4r.x;   // u[x0-1] (clamped)
            const float r1 = okr4 ? r4r.x : r4r.w;   // u[x0+4] (clamped)
            a.x = fmaf(s0, (u1.x + d1.x) + (l1  + c.y), a.x);
            a.y = fmaf(s0, (u1.y + d1.y) + (c.x + c.z), a.y);
            a.z = fmaf(s0, (u1.z + d1.z) + (c.y + c.w), a.z);
            a.w = fmaf(s0, (u1.w + d1.w) + (c.z + r1 ), a.w);
        }

        *reinterpret_cast<float4*>(ob + y * WW + x0) = a;

        // roll in row y+5 (overwrites oldest slot)
        w[t % 9] = ld4(base + min(y + 5, HH - 1) * WW + x0);
    }
}

extern "C" void kernel_launch(void* const* d_in, const int* in_sizes, int n_in,
                              void* d_out, int out_size) {
    const float* u;
    const float* D;
    int nu;
    if (in_sizes[0] > in_sizes[1]) {
        u = (const float*)d_in[0]; D = (const float*)d_in[1]; nu = in_sizes[0];
    } else {
        u = (const float*)d_in[1]; D = (const float*)d_in[0]; nu = in_sizes[1];
    }
    float* out = (float*)d_out;
    const int B = nu / (CC * HH * WW);

    softplus_kernel<<<1, 192>>>(D);

    dim3 blk(32, 4, 1);
    dim3 grd(1, HH / RROWS, B * CC);
    lap_kernel<<<grd, blk>>>(u, out);
}

// round 14
// speedup vs baseline: 1.2992x; 1.2992x over previous
#include <cuda_runtime.h>

#define HH 512
#define WW 512
#define CC 64
#define RROWS 16

__device__ float g_scales[192];

__global__ void softplus_kernel(const float* __restrict__ D) {
    int i = threadIdx.x;
    if (i < 192) {
        float x = D[i];
        g_scales[i] = (x > 20.0f) ? x : log1pf(expf(x));
    }
}

__device__ __forceinline__ float4 ld4(const float* __restrict__ p) {
    return *reinterpret_cast<const float4*>(p);
}
__device__ __forceinline__ float4 f4all(float v) {
    return make_float4(v, v, v, v);
}
__device__ __forceinline__ void pf_l2(const float* p) {
    asm volatile("prefetch.global.L2 [%0];" :: "l"(p));
}

__global__ __launch_bounds__(128, 7) void lap_kernel(const float* __restrict__ u,
                                                     float* __restrict__ out) {
    const int lane = threadIdx.x;                 // 0..31
    const int span = threadIdx.y;                 // 0..3
    const int x0   = (span << 7) + (lane << 2);   // this thread's float4 x
    const int y0   = blockIdx.y * RROWS;
    const int img  = blockIdx.z;
    const int ch   = img & (CC - 1);

    const float* __restrict__ base = u + (size_t)img * (HH * WW);
    float* __restrict__ ob = out + (size_t)img * (HH * WW);

    const float s0 = g_scales[ch];
    const float s1 = g_scales[64 + ch];
    const float s2 = g_scales[128 + ch];
    const float sm4 = -4.0f * (s0 + s1 + s2);

    // branchless clamped x-offsets (uniform per thread, hoisted)
    const int  xl4   = max(x0 - 4, 0);
    const int  xr4   = min(x0 + 4, WW - 4);
    const int  xl16  = max(x0 - 16, 0);
    const int  xr16  = min(x0 + 16, WW - 4);
    const bool okl4  = (x0 >= 4);
    const bool okr4  = (x0 + 4 < WW);
    const bool okl16 = (x0 >= 16);
    const bool okr16 = (x0 + 16 < WW);

    // prefetch the leading-edge rows this block will first-touch:
    // roll-ins y0+5..y0+15 and first d16 rows y0+16..y0+18
#pragma unroll
    for (int i = 5; i < 19; i++)
        pf_l2(base + min(y0 + i, HH - 1) * WW + x0);

    // circular 9-row window: slot (t+i)%9 = row y0+t-4+i (clamped)
    float4 w[9];
#pragma unroll
    for (int i = 0; i < 9; i++) {
        int r = y0 + i - 4;
        r = min(max(r, 0), HH - 1);
        w[i] = ld4(base + r * WW + x0);
    }

#pragma unroll
    for (int t = 0; t < RROWS; t++) {
        const int y = y0 + t;
        const float* __restrict__ rowc = base + y * WW;

        // keep the L2 prefetch pipeline 3 iterations ahead of d16
        pf_l2(base + min(y + 19, HH - 1) * WW + x0);

        // ---- all 6 independent loads issued upfront (MLP) ----
        const float4 u16  = ld4(base + max(y - 16, 0) * WW + x0);
        const float4 d16  = ld4(base + min(y + 16, HH - 1) * WW + x0);
        const float4 l16r = ld4(rowc + xl16);
        const float4 r16r = ld4(rowc + xr16);
        const float4 l4r  = ld4(rowc + xl4);
        const float4 r4r  = ld4(rowc + xr4);

        const float4 c = w[(t + 4) % 9];

        // ---- d=16 contribution ----
        float4 a;
        {
            const float4 l16 = okl16 ? l16r : f4all(l16r.x);
            const float4 r16 = okr16 ? r16r : f4all(r16r.w);
            a.x = fmaf(s2, (u16.x + d16.x) + (l16.x + r16.x), sm4 * c.x);
            a.y = fmaf(s2, (u16.y + d16.y) + (l16.y + r16.y), sm4 * c.y);
            a.z = fmaf(s2, (u16.z + d16.z) + (l16.z + r16.z), sm4 * c.z);
            a.w = fmaf(s2, (u16.w + d16.w) + (l16.w + r16.w), sm4 * c.w);
        }

        // ---- d=4 contribution (verticals from window) ----
        {
            const float4 u4v = w[t % 9];
            const float4 d4v = w[(t + 8) % 9];
            const float4 l4 = okl4 ? l4r : f4all(l4r.x);
            const float4 r4 = okr4 ? r4r : f4all(r4r.w);
            a.x = fmaf(s1, (u4v.x + d4v.x) + (l4.x + r4.x), a.x);
            a.y = fmaf(s1, (u4v.y + d4v.y) + (l4.y + r4.y), a.y);
            a.z = fmaf(s1, (u4v.z + d4v.z) + (l4.z + r4.z), a.z);
            a.w = fmaf(s1, (u4v.w + d4v.w) + (l4.w + r4.w), a.w);
        }

        // ---- d=1 contribution (verticals from window; horiz from l4r/r4r) ----
        {
            const float4 u1 = w[(t + 3) % 9];
            const float4 d1 = w[(t + 5) % 9];
            const float l1 = okl4 ? l4r.w : l4r.x;   // u[x0-1] (clamped)
            const float r1 = okr4 ? r4r.x : r4r.w;   // u[x0+4] (clamped)
            a.x = fmaf(s0, (u1.x + d1.x) + (l1  + c.y), a.x);
            a.y = fmaf(s0, (u1.y + d1.y) + (c.x + c.z), a.y);
            a.z = fmaf(s0, (u1.z + d1.z) + (c.y + c.w), a.z);
            a.w = fmaf(s0, (u1.w + d1.w) + (c.z + r1 ), a.w);
        }

        *reinterpret_cast<float4*>(ob + y * WW + x0) = a;

        // roll in row y+5 (overwrites oldest slot)
        w[t % 9] = ld4(base + min(y + 5, HH - 1) * WW + x0);
    }
}

extern "C" void kernel_launch(void* const* d_in, const int* in_sizes, int n_in,
                              void* d_out, int out_size) {
    const float* u;
    const float* D;
    int nu;
    if (in_sizes[0] > in_sizes[1]) {
        u = (const float*)d_in[0]; D = (const float*)d_in[1]; nu = in_sizes[0];
    } else {
        u = (const float*)d_in[1]; D = (const float*)d_in[0]; nu = in_sizes[1];
    }
    float* out = (float*)d_out;
    const int B = nu / (CC * HH * WW);

    softplus_kernel<<<1, 192>>>(D);

    dim3 blk(32, 4, 1);
    dim3 grd(1, HH / RROWS, B * CC);
    lap_kernel<<<grd, blk>>>(u, out);
}